// round 2
// baseline (speedup 1.0000x reference)
#include <cuda_runtime.h>
#include <cuda_fp16.h>
#include <cuda_bf16.h>

// ---- physical constants (double-precision derived, matching reference) ----
#define KEHALF      7.199822675975274f
#define CUTON_F     2.5f
#define CUTOFF_F    7.5f
#define LRCUT_F     10.0f
#define CUTON16_F   2328306.4365386963f     // 2.5^16
#define CUT_RCONST  0.009999999997526174f   // 10^15 / (10^16 + 2.5^16)^(17/16)
#define CUT_CONST   0.19999999999608f       // (2.5^16+10^16)^(-1/16) + 10^16/(10^16+2.5^16)^(17/16)
#define INV_RANGE   0.2f
#define INV_LR2     0.01f
#define TWO_OVER_LR 0.2f

#define MAX_N 102400
#define MAX_M 2048
#define NSLOT 64            // global scratch slots per bin (spread over L2 slices)

// i-side packed table: (q[i], idx_m[i]) -> one 8B gather = one L2 sector
__device__ float2 d_qm[MAX_N];
// strided global scratch for the REDG share of the reduction
__device__ float  d_scratch[MAX_M * NSLOT];

__global__ void prep_kernel(const float* __restrict__ q,
                            const int* __restrict__ idx_m,
                            int N, float* __restrict__ out, int M) {
    int stride = gridDim.x * blockDim.x;
    int tid = blockIdx.x * blockDim.x + threadIdx.x;
    for (int i = tid; i < N; i += stride)
        d_qm[i] = make_float2(q[i], __int_as_float(idx_m[i]));
    for (int i = tid; i < M; i += stride)
        out[i] = 0.0f;
    for (int i = tid; i < MAX_M * NSLOT; i += stride)
        d_scratch[i] = 0.0f;
}

__device__ __forceinline__ float edge_energy(float x, float y, float z,
                                             float qi, float qj) {
    float s  = fmaf(x, x, fmaf(y, y, z * z));   // d^2
    float rd = rsqrtf(s);                       // 1/d
    float d  = s * rd;                          // d
    float fac = KEHALF * qi * qj;

    // smooth switch: f = sigmoid(-(1/t - 1/(1-t)))
    float f;
    if (d >= CUTOFF_F) {
        f = 0.0f;
    } else if (d <= CUTON_F) {
        f = 1.0f;
    } else {
        float t = (CUTOFF_F - d) * INV_RANGE;
        float g = __fdividef(1.0f, t) - __fdividef(1.0f, 1.0f - t);
        f = __fdividef(1.0f, 1.0f + __expf(g));
    }

    // (d^16 + CUTON16)^(-1/16) via LG2/EX2
    float d4  = s * s;
    float d8  = d4 * d4;
    float d16 = d8 * d8;
    float p   = exp2f(-0.0625f * __log2f(d16 + CUTON16_F));

    float omf    = 1.0f - f;
    float damped = fmaf(omf * CUT_RCONST, d, p - CUT_CONST);
    float coul   = (d < LRCUT_F) ? (rd + fmaf(d, INV_LR2, -TWO_OVER_LR)) : 0.0f;
    return fac * fmaf(f, damped, omf * coul);
}

// main kernel: q table fp16 in shared, i-side packed gather from global,
// reduction split: 3/4 warps -> shared ATOMS, 1/4 warps -> global REDG scratch
__global__ __launch_bounds__(1024, 1)
void energy_smem(const float4* __restrict__ r4,
                 const float*  __restrict__ q,
                 const int4*   __restrict__ ii4,
                 const int4*   __restrict__ jj4,
                 const float*  __restrict__ r_scalar,
                 const int*    __restrict__ idx_i,
                 const int*    __restrict__ idx_j,
                 int N, int P, float* __restrict__ out, int M) {
    extern __shared__ char sraw[];
    __half* qtab = (__half*)sraw;
    float*  ymol = (float*)(sraw + ((2 * N + 15) & ~15));

    // stage q as fp16 into shared (coalesced float2 -> half2)
    const float2* q2  = (const float2*)q;
    __half2*      qt2 = (__half2*)qtab;
    for (int i = threadIdx.x; i < (N >> 1); i += blockDim.x)
        qt2[i] = __float22half2_rn(q2[i]);
    if ((N & 1) && threadIdx.x == 0)
        qtab[N - 1] = __float2half_rn(q[N - 1]);
    for (int b = threadIdx.x; b < M; b += blockDim.x) ymol[b] = 0.0f;
    __syncthreads();

    int wid_in_blk = threadIdx.x >> 5;
    int gwarp      = blockIdx.x * (blockDim.x >> 5) + wid_in_blk;
    bool use_red   = (wid_in_blk & 3) == 3;          // 1 of 4 warps -> global REDG
    int slot       = gwarp & (NSLOT - 1);

    int gid    = blockIdx.x * blockDim.x + threadIdx.x;
    int stride = gridDim.x * blockDim.x;
    int P4 = P >> 2;

    for (int g = gid; g < P4; g += stride) {
        // coalesced streams (evict-first: one-pass data, keep tables in L2)
        float4 a = __ldcs(&r4[3 * g + 0]);
        float4 b = __ldcs(&r4[3 * g + 1]);
        float4 c = __ldcs(&r4[3 * g + 2]);
        int4 ii = __ldcs(&ii4[g]);
        int4 jj = __ldcs(&jj4[g]);

        // i-side gathers (global, 1 sector each), issued together for MLP
        float2 m0 = d_qm[ii.x];
        float2 m1 = d_qm[ii.y];
        float2 m2 = d_qm[ii.z];
        float2 m3 = d_qm[ii.w];
        // j-side gathers from shared fp16 table (smem crossbar, not L1tex)
        float qj0 = __half2float(qtab[jj.x]);
        float qj1 = __half2float(qtab[jj.y]);
        float qj2 = __half2float(qtab[jj.z]);
        float qj3 = __half2float(qtab[jj.w]);

        float e0 = edge_energy(a.x, a.y, a.z, m0.x, qj0);
        float e1 = edge_energy(a.w, b.x, b.y, m1.x, qj1);
        float e2 = edge_energy(b.z, b.w, c.x, m2.x, qj2);
        float e3 = edge_energy(c.y, c.z, c.w, m3.x, qj3);

        if (use_red) {
            atomicAdd(&d_scratch[__float_as_int(m0.y) * NSLOT + slot], e0);
            atomicAdd(&d_scratch[__float_as_int(m1.y) * NSLOT + slot], e1);
            atomicAdd(&d_scratch[__float_as_int(m2.y) * NSLOT + slot], e2);
            atomicAdd(&d_scratch[__float_as_int(m3.y) * NSLOT + slot], e3);
        } else {
            atomicAdd(&ymol[__float_as_int(m0.y)], e0);
            atomicAdd(&ymol[__float_as_int(m1.y)], e1);
            atomicAdd(&ymol[__float_as_int(m2.y)], e2);
            atomicAdd(&ymol[__float_as_int(m3.y)], e3);
        }
    }

    // scalar tail
    for (int e = (P4 << 2) + gid; e < P; e += stride) {
        float x = r_scalar[3 * e + 0];
        float y = r_scalar[3 * e + 1];
        float z = r_scalar[3 * e + 2];
        float2 mi = d_qm[idx_i[e]];
        float qj  = __half2float(qtab[idx_j[e]]);
        float ev  = edge_energy(x, y, z, mi.x, qj);
        atomicAdd(&ymol[__float_as_int(mi.y)], ev);
    }

    __syncthreads();
    for (int b = threadIdx.x; b < M; b += blockDim.x) {
        float v = ymol[b];
        if (v != 0.0f) atomicAdd(&out[b], v);
    }
}

// fold the REDG scratch into out (runs after energy_smem in-stream)
__global__ void combine_kernel(float* __restrict__ out, int M) {
    int b = blockIdx.x * blockDim.x + threadIdx.x;
    if (b < M) {
        float s = 0.0f;
        const float* row = &d_scratch[b * NSLOT];
        #pragma unroll
        for (int k = 0; k < NSLOT; k++) s += row[k];
        out[b] += s;
    }
}

// fallback (shapes outside the smem-table design): global atomics directly
__global__ __launch_bounds__(256)
void energy_fallback(const float* __restrict__ r_scalar,
                     const float* __restrict__ q,
                     const int*   __restrict__ idx_i,
                     const int*   __restrict__ idx_j,
                     const int*   __restrict__ idx_m,
                     int P, float* __restrict__ out) {
    int gid    = blockIdx.x * blockDim.x + threadIdx.x;
    int stride = gridDim.x * blockDim.x;
    for (int e = gid; e < P; e += stride) {
        float x = r_scalar[3 * e + 0];
        float y = r_scalar[3 * e + 1];
        float z = r_scalar[3 * e + 2];
        int i = idx_i[e];
        float ev = edge_energy(x, y, z, q[i], q[idx_j[e]]);
        atomicAdd(&out[idx_m[i]], ev);
    }
}

extern "C" void kernel_launch(void* const* d_in, const int* in_sizes, int n_in,
                              void* d_out, int out_size) {
    // metadata order: atomic_numbers, q, r_ij, idx_i, idx_j, idx_m, maxm
    const float* q     = (const float*)d_in[1];
    const float* r_ij  = (const float*)d_in[2];
    const int*   idx_i = (const int*)d_in[3];
    const int*   idx_j = (const int*)d_in[4];
    const int*   idx_m = (const int*)d_in[5];
    int N = in_sizes[1];
    int P = in_sizes[3];
    int M = out_size;
    float* out = (float*)d_out;

    if (N > MAX_N || M > MAX_M) {
        // simple correct fallback
        prep_kernel<<<512, 256>>>(q, idx_m, 0, out, M);  // zero out only
        energy_fallback<<<1184, 256>>>(r_ij, q, idx_i, idx_j, idx_m, P, out);
        return;
    }

    prep_kernel<<<512, 256>>>(q, idx_m, N, out, M);

    int sm_count = 148;
    cudaDeviceGetAttribute(&sm_count, cudaDevAttrMultiProcessorCount, 0);

    size_t smem_bytes = ((size_t)2 * N + 15 & ~(size_t)15) + (size_t)4 * M;
    static bool attr_set = false;
    cudaFuncSetAttribute(energy_smem, cudaFuncAttributeMaxDynamicSharedMemorySize,
                         (int)smem_bytes);
    (void)attr_set;

    energy_smem<<<sm_count, 1024, smem_bytes>>>(
        (const float4*)r_ij, q, (const int4*)idx_i, (const int4*)idx_j,
        r_ij, idx_i, idx_j, N, P, out, M);

    combine_kernel<<<(M + 255) / 256, 256>>>(out, M);
}